// round 14
// baseline (speedup 1.0000x reference)
#include <cuda_runtime.h>
#include <cuda_bf16.h>
#include <math.h>
#include <stdint.h>

#define NPTS 32768
#define KK 32
#define DD 64
#define LOG_2PI 1.8378770664093453f

// tcgen05 is arch-SPECIFIC (sm_103a). The harness also builds a plain
// compute_103 PTX pass, which must not see tcgen05 instructions.
#if defined(__CUDA_ARCH__) && (defined(__CUDA_ARCH_FEAT_SM103_ALL) || \
    defined(__CUDA_ARCH_FEAT_SM100_ALL) || defined(__CUDA_ARCH_FEAT_SM101_ALL) || \
    defined(__CUDA_ARCH_FEAT_SM110_ALL) || defined(__CUDA_ARCH_FEAT_SM120_ALL))
#define USE_TC 1
#else
#define USE_TC 0
#endif

// ---------------- device scratch ----------------
// per-k B tile: [hi 16KB][lo 16KB]; each = 64 rows x 128 K-cols bf16,
// blocked SW128 atoms (8 rows x 64 bf16 = 1024B; atom_off = arow + acol*8)
__device__ __align__(16) unsigned char g_Bcat[KK * 32768];
__device__ __align__(16) float g_Wf[KK][64 * 68];   // fp32 W~ rows (fallback path)
__device__ float g_ck[KK];
__device__ float g_rm[128], g_rs[128];

// ---------------- common helpers ----------------
__device__ __forceinline__ unsigned smem_u32(const void* p) {
    unsigned r;
    asm("{ .reg .u64 t; cvta.to.shared.u64 t, %1; cvt.u32.u64 %0, t; }" : "=r"(r) : "l"(p));
    return r;
}
#define MBAR_INIT(addr, cnt) \
    asm volatile("mbarrier.init.shared.b64 [%0], %1;" :: "r"(addr), "r"(cnt) : "memory")
#define MBAR_EXPECT_TX(addr, bytes) \
    asm volatile("mbarrier.arrive.expect_tx.shared.b64 _, [%0], %1;" :: "r"(addr), "r"(bytes) : "memory")
#define MBAR_ARRIVE(addr) \
    asm volatile("mbarrier.arrive.shared.b64 _, [%0];" :: "r"(addr) : "memory")
#define MBAR_WAIT(addr, parity) \
    asm volatile("{\n\t.reg .pred P;\n\tWL_%=:\n\t" \
        "mbarrier.try_wait.parity.acquire.cta.shared::cta.b64 P, [%0], %1, 0x989680;\n\t" \
        "@P bra.uni WD_%=;\n\tbra.uni WL_%=;\n\tWD_%=:\n\t}" \
        :: "r"(addr), "r"(parity) : "memory")
#define BULK_CP(dst, src, bytes, bar) \
    asm volatile("cp.async.bulk.shared::cluster.global.mbarrier::complete_tx::bytes [%0], [%1], %2, [%3];" \
        :: "r"(dst), "l"(src), "r"(bytes), "r"(bar) : "memory")

#if USE_TC
// ---------------- tcgen05 helpers (sm_103a-only) ----------------
#define T_ALLOC(smaddr, n) \
    asm volatile("tcgen05.alloc.cta_group::1.sync.aligned.shared::cta.b32 [%0], %1;" :: "r"(smaddr), "r"(n) : "memory")
#define T_DEALLOC(t, n) \
    asm volatile("tcgen05.dealloc.cta_group::1.sync.aligned.b32 %0, %1;" :: "r"(t), "r"(n))
#define T_COMMIT(bar) \
    asm volatile("tcgen05.commit.cta_group::1.mbarrier::arrive::one.shared::cluster.b64 [%0];" :: "r"(bar) : "memory")
#define T_FENCE_AFTER()  asm volatile("tcgen05.fence::after_thread_sync;" ::: "memory")
#define T_FENCE_BEFORE() asm volatile("tcgen05.fence::before_thread_sync;" ::: "memory")
#define T_WAIT_LD()      asm volatile("tcgen05.wait::ld.sync.aligned;" ::: "memory")
#define T_WAIT_ST()      asm volatile("tcgen05.wait::st.sync.aligned;" ::: "memory")

#define T_LD_X32(r, tmem_addr) \
    asm volatile( \
        "tcgen05.ld.sync.aligned.32x32b.x32.b32 " \
        "{%0, %1, %2, %3, %4, %5, %6, %7, " \
        " %8, %9, %10, %11, %12, %13, %14, %15, " \
        " %16, %17, %18, %19, %20, %21, %22, %23, " \
        " %24, %25, %26, %27, %28, %29, %30, %31}, [%32];" \
        : "=r"((r)[0]),  "=r"((r)[1]),  "=r"((r)[2]),  "=r"((r)[3]), \
          "=r"((r)[4]),  "=r"((r)[5]),  "=r"((r)[6]),  "=r"((r)[7]), \
          "=r"((r)[8]),  "=r"((r)[9]),  "=r"((r)[10]), "=r"((r)[11]), \
          "=r"((r)[12]), "=r"((r)[13]), "=r"((r)[14]), "=r"((r)[15]), \
          "=r"((r)[16]), "=r"((r)[17]), "=r"((r)[18]), "=r"((r)[19]), \
          "=r"((r)[20]), "=r"((r)[21]), "=r"((r)[22]), "=r"((r)[23]), \
          "=r"((r)[24]), "=r"((r)[25]), "=r"((r)[26]), "=r"((r)[27]), \
          "=r"((r)[28]), "=r"((r)[29]), "=r"((r)[30]), "=r"((r)[31]) \
        : "r"(tmem_addr))

#define T_ST_X32(tmem_addr, r) \
    asm volatile( \
        "tcgen05.st.sync.aligned.32x32b.x32.b32 [%0], " \
        "{%1, %2, %3, %4, %5, %6, %7, %8, " \
        " %9, %10, %11, %12, %13, %14, %15, %16, " \
        " %17, %18, %19, %20, %21, %22, %23, %24, " \
        " %25, %26, %27, %28, %29, %30, %31, %32};" \
        :: "r"(tmem_addr), \
           "r"((r)[0]),  "r"((r)[1]),  "r"((r)[2]),  "r"((r)[3]), \
           "r"((r)[4]),  "r"((r)[5]),  "r"((r)[6]),  "r"((r)[7]), \
           "r"((r)[8]),  "r"((r)[9]),  "r"((r)[10]), "r"((r)[11]), \
           "r"((r)[12]), "r"((r)[13]), "r"((r)[14]), "r"((r)[15]), \
           "r"((r)[16]), "r"((r)[17]), "r"((r)[18]), "r"((r)[19]), \
           "r"((r)[20]), "r"((r)[21]), "r"((r)[22]), "r"((r)[23]), \
           "r"((r)[24]), "r"((r)[25]), "r"((r)[26]), "r"((r)[27]), \
           "r"((r)[28]), "r"((r)[29]), "r"((r)[30]), "r"((r)[31]) \
        : "memory")

#define T_ST_X8(tmem_addr, r) \
    asm volatile( \
        "tcgen05.st.sync.aligned.32x32b.x8.b32 [%0], " \
        "{%1, %2, %3, %4, %5, %6, %7, %8};" \
        :: "r"(tmem_addr), \
           "r"((r)[0]), "r"((r)[1]), "r"((r)[2]), "r"((r)[3]), \
           "r"((r)[4]), "r"((r)[5]), "r"((r)[6]), "r"((r)[7]) \
        : "memory")

// SW128 K-major smem descriptor (verified layout)
__device__ __forceinline__ uint64_t make_desc(uint32_t addr) {
    const uint64_t base = (uint64_t(2) << 61) | (uint64_t(1) << 46) |
                          (uint64_t(64) << 32) | (uint64_t(1) << 16);
    return base | ((uint64_t)(addr >> 4) & 0x3FFF);
}

// cg1 bf16 TS MMA (A in TMEM): idesc dtype F32, a/b BF16, N=64, M=128
#define MMA_IDESC 0x8100490u
__device__ __forceinline__ void mma_f16_ts(uint32_t d, uint32_t a, uint64_t b, uint32_t en) {
    asm volatile(
        "{\n\t.reg .pred p;\n\tsetp.ne.u32 p, %4, 0;\n\t"
        "tcgen05.mma.cta_group::1.kind::f16 [%0], [%1], %2, %3, {%5, %5, %5, %5}, p;\n\t}"
        :: "r"(d), "r"(a), "l"(b), "r"(MMA_IDESC), "r"(en), "r"(0u) : "memory");
}

// 15 K-steps, K=80: (Ahi,Bhi)x5 + (Alo,Bhi)x5 + (Ahi,Blo)x5
__device__ __forceinline__ void issue_mma_k(uint32_t dtm, uint32_t ahi, uint32_t alo, uint64_t bhi) {
    const int acol[5] = {0, 8, 16, 24, 32};
    const int boff[5] = {0, 2, 4, 6, 512};
    uint64_t blo = bhi + 1024;                // lo half at +16384B
    uint32_t en = 0;
#pragma unroll
    for (int s = 0; s < 5; s++) { mma_f16_ts(dtm, ahi + acol[s], bhi + boff[s], en); en = 1; }
#pragma unroll
    for (int s = 0; s < 5; s++) mma_f16_ts(dtm, alo + acol[s], bhi + boff[s], 1);
#pragma unroll
    for (int s = 0; s < 5; s++) mma_f16_ts(dtm, ahi + acol[s], blo + boff[s], 1);
}
#endif  // USE_TC

// ============= setup v2: chol(Sigma)=C (1 warp) -> W=C^{-1} (col-parallel) -> pack =============
// maha = ||W(x-mu)||^2 since Sinv = W^T W;  logdet = 2*sum log C_jj
extern __shared__ float dsm[];
__global__ void __launch_bounds__(512) setup_kernel(const float* __restrict__ L,
                                                    const float* __restrict__ mu,
                                                    const float* __restrict__ w) {
    float* Lt = dsm;                 // [64][65]: L^T, later reused as Wm (W, row-major [i][c])
    float* A  = dsm + 64 * 65;       // [64][65]: Sigma (lower) -> C (Cholesky factor)
    float* Wm = Lt;
    __shared__ float pivs[64], invd[64], colmu[64], ubuf[64];
    int k = blockIdx.x, tid = threadIdx.x, lane = tid & 31;

    // load L transposed: Lt[m][d] = L[k][d][m]
    for (int i = tid; i < DD * DD; i += 512) {
        int d = i >> 6, m = i & 63;
        Lt[m * 65 + d] = L[(size_t)k * DD * DD + i];
    }
    __syncthreads();

    // Sigma lower triangle: A[d][e] = delta + sum_{m<=e} Lt[m][d]*Lt[m][e], e <= d
    for (int i = tid; i < DD * DD; i += 512) {
        int d = i >> 6, e = i & 63;
        if (e <= d) {
            float s = (d == e) ? 1.0f : 0.0f;
            for (int m = 0; m <= e; m++) s = fmaf(Lt[m * 65 + d], Lt[m * 65 + e], s);
            A[d * 65 + e] = s;
        }
    }
    __syncthreads();

    // ---- single-warp Cholesky of A (lower), only __syncwarp between phases ----
    if (tid < 32) {
#pragma unroll 1
        for (int j = 0; j < DD; j++) {
            if (lane == 0) {
                float dj = sqrtf(A[j * 65 + j]);
                A[j * 65 + j] = dj;
                pivs[j] = dj;
                invd[j] = 1.0f / dj;
            }
            __syncwarp();
            float inv = invd[j];
            for (int r = j + 1 + lane; r < DD; r += 32) A[r * 65 + j] *= inv;
            __syncwarp();
            for (int r = j + 1 + lane; r < DD; r += 32) {
                float lv = A[r * 65 + j];
                for (int c = j + 1; c <= r; c++)
                    A[r * 65 + c] = fmaf(-lv, A[c * 65 + j], A[r * 65 + c]);
            }
            __syncwarp();
        }
    }
    __syncthreads();

    // ---- W = C^{-1}: 8 threads per column, no block barriers ----
    // column j: W[j][j] = 1/C_jj; for i>j: W[i][j] = -(sum_{m=j}^{i-1} C[i][m] W[m][j]) / C_ii
    {
        int j = tid >> 3, s8 = tid & 7;
        if (s8 == 0) Wm[j * 65 + j] = invd[j];
        __syncwarp();
#pragma unroll 1
        for (int i = 1; i < DD; i++) {
            float p = 0.f;
            if (i > j) {
                for (int m = j + s8; m < i; m += 8)
                    p = fmaf(A[i * 65 + m], Wm[m * 65 + j], p);
            }
            p += __shfl_xor_sync(0xffffffffu, p, 1, 8);
            p += __shfl_xor_sync(0xffffffffu, p, 2, 8);
            p += __shfl_xor_sync(0xffffffffu, p, 4, 8);
            if (i > j && s8 == 0) Wm[i * 65 + j] = -p * invd[i];
            __syncwarp();
        }
    }
    if (tid < 64) colmu[tid] = mu[k * DD + tid];
    if (tid >= 448) {   // last warps compute logs while others trisolve — cheap anyway
    }
    __syncthreads();

    // ---- u = W mu (8 threads per ROW j: u[j] = sum_{c<=j} W[j][c] mu[c]) ----
    {
        int j = tid >> 3, s8 = tid & 7;
        float p = 0.f;
        for (int c = s8; c <= j; c += 8) p = fmaf(Wm[j * 65 + c], colmu[c], p);
        p += __shfl_xor_sync(0xffffffffu, p, 1, 8);
        p += __shfl_xor_sync(0xffffffffu, p, 2, 8);
        p += __shfl_xor_sync(0xffffffffu, p, 4, 8);
        if (s8 == 0) ubuf[j] = p;
    }
    if (tid < 64) pivs[tid] = logf(pivs[tid]);
    __syncthreads();

    // ---- pack W~ = [W | -W mu | 0...] hi/lo bf16 blocked-atom SW128 + fp32 copy ----
    // row j of W~: cols c<=j -> W[j][c]; col 64 -> -u[j]
    for (int idx = tid; idx < 64 * 128; idx += 512) {
        int j = idx >> 7, c = idx & 127;
        float v = 0.f;
        if (c < 64) { if (c <= j) v = Wm[j * 65 + c]; }
        else if (c == 64) v = -ubuf[j];
        __nv_bfloat16 hi = __float2bfloat16(v);
        __nv_bfloat16 lo = __float2bfloat16(v - __bfloat162float(hi));
        uint32_t byte = (uint32_t)(((j >> 3) + (c >> 6) * 8) * 1024 + (j & 7) * 128 + (c & 63) * 2);
        uint32_t sw = byte ^ ((byte >> 3) & 0x70);
        *(__nv_bfloat16*)(g_Bcat + (size_t)k * 32768 + sw) = hi;
        *(__nv_bfloat16*)(g_Bcat + (size_t)k * 32768 + 16384 + sw) = lo;
        if (c < 68) g_Wf[k][j * 68 + c] = v;
    }
    // ck = log_softmax(w)[k] - 0.5*(D log2pi + 2*sum log C_jj)
    if (tid < 32) {
        float ldv = pivs[tid] + pivs[tid + 32];
        for (int o = 16; o; o >>= 1) ldv += __shfl_xor_sync(0xffffffffu, ldv, o);
        ldv *= 2.0f;
        float wv = w[tid];
        float mxw = wv;
        for (int o = 16; o; o >>= 1) mxw = fmaxf(mxw, __shfl_xor_sync(0xffffffffu, mxw, o));
        float se = __expf(wv - mxw);
        for (int o = 16; o; o >>= 1) se += __shfl_xor_sync(0xffffffffu, se, o);
        float lgk = __shfl_sync(0xffffffffu, wv - (mxw + logf(se)), k);
        if (tid == 0) g_ck[k] = lgk - 0.5f * (DD * LOG_2PI + ldv);
    }
}

// ============= main: 256 points/CTA (2 MMA tiles), warp-specialized producer =============
// TMEM (alloc 512): A0hi 0..39, A0lo 40..79, A1hi 80..119, A1lo 120..159,
//                   D(g,b) = 160 + g*128 + b*64
// dyn smem: 3 x 32KB B ring (+1KB align)
// barriers: s_bar[0,1]=mma_done(cnt 1), [2,3]=cons(cnt 8), [4,5,6]=bfull(cnt 1)
__global__ void __launch_bounds__(288, 1) main_kernel(const float* __restrict__ X) {
#if USE_TC
    extern __shared__ char msm[];
    __shared__ unsigned long long s_bar[7];
    __shared__ uint32_t s_tmem;
    __shared__ float s_ck[KK];
    __shared__ float s_wm[9], s_ws[9];

    uint32_t raw = smem_u32(msm);
    uint32_t sbase = (raw + 1023u) & ~1023u;
    int tx = threadIdx.x, wid = tx >> 5, lane = tx & 31;

    if (wid == 0) T_ALLOC(smem_u32(&s_tmem), 512);
    if (tx == 0) {
        MBAR_INIT(smem_u32(&s_bar[0]), 1);
        MBAR_INIT(smem_u32(&s_bar[1]), 1);
        MBAR_INIT(smem_u32(&s_bar[2]), 8);
        MBAR_INIT(smem_u32(&s_bar[3]), 8);
        MBAR_INIT(smem_u32(&s_bar[4]), 1);
        MBAR_INIT(smem_u32(&s_bar[5]), 1);
        MBAR_INIT(smem_u32(&s_bar[6]), 1);
    }
    if (tx < KK) s_ck[tx] = g_ck[tx];
    __syncthreads();

    uint32_t tmem;
    asm volatile("ld.shared.b32 %0, [%1];" : "=r"(tmem) : "r"(smem_u32(&s_tmem)));

    // producer: kick off B ring prologue copies (k=0,1,2) immediately
    if (tx == 256) {
#pragma unroll
        for (int q = 0; q < 3; q++) {
            unsigned bf = smem_u32(&s_bar[4 + q]);
            MBAR_EXPECT_TX(bf, 32768u);
            BULK_CP(sbase + q * 32768u, g_Bcat + (size_t)q * 32768u, 32768u, bf);
        }
    }

    // consumers: build A (both tiles) in TMEM
    if (tx < 256) {
        int g = tx >> 7, gtx = tx & 127;
        const float4* xs = (const float4*)(X + ((size_t)blockIdx.x * 256 + g * 128 + gtx) * DD);
        uint32_t warp_off = (uint32_t)((gtx >> 5) << 21);
        uint32_t h[40], l[40];
#pragma unroll
        for (int i = 0; i < 16; i++) {
            float4 v = xs[i];
            float x0 = v.x, x1 = v.y, x2 = v.z, x3 = v.w;
            __nv_bfloat162 hp0, hp1, lp0, lp1;
            hp0.x = __float2bfloat16(x0); hp0.y = __float2bfloat16(x1);
            hp1.x = __float2bfloat16(x2); hp1.y = __float2bfloat16(x3);
            lp0.x = __float2bfloat16(x0 - __bfloat162float(hp0.x));
            lp0.y = __float2bfloat16(x1 - __bfloat162float(hp0.y));
            lp1.x = __float2bfloat16(x2 - __bfloat162float(hp1.x));
            lp1.y = __float2bfloat16(x3 - __bfloat162float(hp1.y));
            h[2 * i]     = *(uint32_t*)&hp0;
            h[2 * i + 1] = *(uint32_t*)&hp1;
            l[2 * i]     = *(uint32_t*)&lp0;
            l[2 * i + 1] = *(uint32_t*)&lp1;
        }
        {
            __nv_bfloat162 one; one.x = __float2bfloat16(1.0f); one.y = __float2bfloat16(0.0f);
            h[32] = *(uint32_t*)&one;
            l[32] = 0u;
#pragma unroll
            for (int i = 33; i < 40; i++) { h[i] = 0u; l[i] = 0u; }
        }
        uint32_t abase = tmem + (uint32_t)(g * 80);
        T_ST_X32(abase + 0 + warp_off, h);
        T_ST_X8(abase + 32 + warp_off, h + 32);
        T_ST_X32(abase + 40 + warp_off, l);
        T_ST_X8(abase + 72 + warp_off, l + 32);
        T_WAIT_ST();
        T_FENCE_BEFORE();
    }
    __syncthreads();    // A ready in TMEM for producer's MMAs

    // ---------------- producer warp: MMA issue + B prefetch ----------------
    if (tx == 256) {
        T_FENCE_AFTER();
#pragma unroll 1
        for (int k = 0; k < KK; k++) {
            int b = k & 1;
            int q = k - (k / 3) * 3;
            MBAR_WAIT(smem_u32(&s_bar[4 + q]), (k / 3) & 1);             // B(k) in smem
            if (k >= 2) MBAR_WAIT(smem_u32(&s_bar[2 + b]), ((k - 2) >> 1) & 1);  // D[b] free
            uint64_t bd = make_desc(sbase + q * 32768u);
            issue_mma_k(tmem + 160 + b * 64, tmem + 0,  tmem + 40,  bd);  // tile 0
            issue_mma_k(tmem + 288 + b * 64, tmem + 80, tmem + 120, bd);  // tile 1
            T_COMMIT(smem_u32(&s_bar[b]));
            if (k + 3 < KK) {
                MBAR_WAIT(smem_u32(&s_bar[b]), (k >> 1) & 1);            // MMA(k) done -> B[q] free
                unsigned bf = smem_u32(&s_bar[4 + q]);
                MBAR_EXPECT_TX(bf, 32768u);
                BULK_CP(sbase + q * 32768u, g_Bcat + (size_t)(k + 3) * 32768u, 32768u, bf);
            }
        }
    }

    // ---------------- consumer warps: epilogue + online LSE ----------------
    float mx = -INFINITY, sm = 0.f;
    if (tx < 256) {
        int g = tx >> 7;
        uint32_t dbase = tmem + 160 + (uint32_t)(g * 128);
#pragma unroll 1
        for (int k = 0; k < KK; k++) {
            int b = k & 1;
            MBAR_WAIT(smem_u32(&s_bar[b]), (k >> 1) & 1);
            T_FENCE_AFTER();
            uint32_t dr[64];
            T_LD_X32(dr, dbase + b * 64);
            T_LD_X32(dr + 32, dbase + b * 64 + 32);
            T_WAIT_LD();
            if (lane == 0) MBAR_ARRIVE(smem_u32(&s_bar[2 + b]));   // D reads retired
            float m0 = 0.f, m1 = 0.f, m2 = 0.f, m3 = 0.f;
#pragma unroll
            for (int j = 0; j < 16; j++) {
                float a = __uint_as_float(dr[4 * j]);
                float b2 = __uint_as_float(dr[4 * j + 1]);
                float c = __uint_as_float(dr[4 * j + 2]);
                float d = __uint_as_float(dr[4 * j + 3]);
                m0 = fmaf(a, a, m0);
                m1 = fmaf(b2, b2, m1);
                m2 = fmaf(c, c, m2);
                m3 = fmaf(d, d, m3);
            }
            float logp = s_ck[k] - 0.5f * ((m0 + m1) + (m2 + m3));
            if (logp > mx) { sm = fmaf(sm, __expf(mx - logp), 1.0f); mx = logp; }
            else           { sm += __expf(logp - mx); }
        }
    }

    // block LSE reduce -> per-CTA (M, S)
    if (tx < 256) {
#pragma unroll
        for (int o = 16; o; o >>= 1) {
            float m2 = __shfl_xor_sync(0xffffffffu, mx, o);
            float s2 = __shfl_xor_sync(0xffffffffu, sm, o);
            float M = fmaxf(mx, m2);
            sm = sm * __expf(mx - M) + s2 * __expf(m2 - M);
            mx = M;
        }
        if (lane == 0) { s_wm[wid] = mx; s_ws[wid] = sm; }
    }
    __syncthreads();
    if (tx < 8) {
        float m = s_wm[tx], s = s_ws[tx];
#pragma unroll
        for (int o = 4; o; o >>= 1) {
            float m2 = __shfl_xor_sync(0xffu, m, o);
            float s2 = __shfl_xor_sync(0xffu, s, o);
            float M = fmaxf(m, m2);
            s = s * __expf(m - M) + s2 * __expf(m2 - M);
            m = M;
        }
        if (tx == 0) { g_rm[blockIdx.x] = m; g_rs[blockIdx.x] = s; }
    }
    __syncthreads();
    if (wid == 0) T_DEALLOC(tmem, 512);
#else
    // ---------- generic scalar fallback: maha = || W~ x~ ||^2 ----------
    extern __shared__ char msm[];
    float* sW = (float*)msm;                  // [64*68] fp32 W~ for current k
    __shared__ float s_ck[KK];
    __shared__ float s_wm[9], s_ws[9];
    int tx = threadIdx.x, wid = tx >> 5, lane = tx & 31;
    if (tx < KK) s_ck[tx] = g_ck[tx];

    float xt[65];
    if (tx < 256) {
        const float4* xs = (const float4*)(X + ((size_t)blockIdx.x * 256 + tx) * DD);
#pragma unroll
        for (int i = 0; i < 16; i++) {
            float4 v = xs[i];
            xt[4 * i] = v.x; xt[4 * i + 1] = v.y; xt[4 * i + 2] = v.z; xt[4 * i + 3] = v.w;
        }
        xt[64] = 1.0f;
    }

    float mx = -INFINITY, sm = 0.f;
#pragma unroll 1
    for (int k = 0; k < KK; k++) {
        __syncthreads();
        const float4* src = (const float4*)g_Wf[k];
        for (int i = tx; i < 64 * 68 / 4; i += 288) ((float4*)sW)[i] = src[i];
        __syncthreads();
        if (tx < 256) {
            float maha = 0.f;
            for (int j = 0; j < 64; j++) {
                const float* row = sW + j * 68;
                float z = 0.f;
#pragma unroll
                for (int c = 0; c < 65; c++) z = fmaf(row[c], xt[c], z);
                maha = fmaf(z, z, maha);
            }
            float logp = s_ck[k] - 0.5f * maha;
            if (logp > mx) { sm = fmaf(sm, __expf(mx - logp), 1.0f); mx = logp; }
            else           { sm += __expf(logp - mx); }
        }
    }
    if (tx < 256) {
#pragma unroll
        for (int o = 16; o; o >>= 1) {
            float m2 = __shfl_xor_sync(0xffffffffu, mx, o);
            float s2 = __shfl_xor_sync(0xffffffffu, sm, o);
            float M = fmaxf(mx, m2);
            sm = sm * __expf(mx - M) + s2 * __expf(m2 - M);
            mx = M;
        }
        if (lane == 0) { s_wm[wid] = mx; s_ws[wid] = sm; }
    }
    __syncthreads();
    if (tx < 8) {
        float m = s_wm[tx], s = s_ws[tx];
#pragma unroll
        for (int o = 4; o; o >>= 1) {
            float m2 = __shfl_xor_sync(0xffu, m, o);
            float s2 = __shfl_xor_sync(0xffu, s, o);
            float M = fmaxf(m, m2);
            s = s * __expf(m - M) + s2 * __expf(m2 - M);
            m = M;
        }
        if (tx == 0) { g_rm[blockIdx.x] = m; g_rs[blockIdx.x] = s; }
    }
#endif
}

// ============= final reduce: -logsumexp over 128 CTA partials =============
__global__ void reduce_kernel(float* __restrict__ out) {
    __shared__ float rm[4], rs[4];
    int tx = threadIdx.x, lane = tx & 31, wid = tx >> 5;
    float m = g_rm[tx], s = g_rs[tx];
#pragma unroll
    for (int o = 16; o; o >>= 1) {
        float m2 = __shfl_xor_sync(0xffffffffu, m, o);
        float s2 = __shfl_xor_sync(0xffffffffu, s, o);
        float M = fmaxf(m, m2);
        s = s * __expf(m - M) + s2 * __expf(m2 - M);
        m = M;
    }
    if (lane == 0) { rm[wid] = m; rs[wid] = s; }
    __syncthreads();
    if (tx < 4) {
        float mm = rm[tx], ss = rs[tx];
#pragma unroll
        for (int o = 2; o; o >>= 1) {
            float m2 = __shfl_xor_sync(0xfu, mm, o);
            float s2 = __shfl_xor_sync(0xfu, ss, o);
            float M = fmaxf(mm, m2);
            ss = ss * __expf(mm - M) + s2 * __expf(m2 - M);
            mm = M;
        }
        if (tx == 0) out[0] = -(mm + logf(ss));
    }
}

// ---------------- launch ----------------
extern "C" void kernel_launch(void* const* d_in, const int* in_sizes, int n_in,
                              void* d_out, int out_size) {
    const float* X  = (const float*)d_in[0];
    const float* mu = (const float*)d_in[1];
    const float* L  = (const float*)d_in[2];
    const float* w  = (const float*)d_in[3];
    float* out = (float*)d_out;

    static int attr_done = 0;
    if (!attr_done) {
        cudaFuncSetAttribute(setup_kernel, cudaFuncAttributeMaxDynamicSharedMemorySize, 33280);
        cudaFuncSetAttribute(main_kernel, cudaFuncAttributeMaxDynamicSharedMemorySize, 99328);
        attr_done = 1;
    }

    setup_kernel<<<KK, 512, 33280>>>(L, mu, w);
    main_kernel<<<NPTS / 256, 288, 99328>>>(X);
    reduce_kernel<<<1, 128>>>(out);
}

// round 15
// speedup vs baseline: 2.3741x; 2.3741x over previous
#include <cuda_runtime.h>
#include <cuda_bf16.h>
#include <math.h>
#include <stdint.h>

#define NPTS 32768
#define KK 32
#define DD 64
#define LOG_2PI 1.8378770664093453f

// tcgen05 is arch-SPECIFIC (sm_103a). The harness also builds a plain
// compute_103 PTX pass, which must not see tcgen05 instructions.
#if defined(__CUDA_ARCH__) && (defined(__CUDA_ARCH_FEAT_SM103_ALL) || \
    defined(__CUDA_ARCH_FEAT_SM100_ALL) || defined(__CUDA_ARCH_FEAT_SM101_ALL) || \
    defined(__CUDA_ARCH_FEAT_SM110_ALL) || defined(__CUDA_ARCH_FEAT_SM120_ALL))
#define USE_TC 1
#else
#define USE_TC 0
#endif

// ---------------- device scratch ----------------
// per-k B tile: [hi 16KB][lo 16KB]; each = 64 rows x 128 K-cols bf16,
// blocked SW128 atoms (8 rows x 64 bf16 = 1024B; atom_off = arow + acol*8)
// row j of B~ = [Sinv row j | -2*b_j | 0...], b = Sinv*mu
__device__ __align__(16) unsigned char g_Bcat[KK * 32768];
__device__ __align__(16) float g_Wf[KK][64 * 68];   // fp32 B~ rows (fallback path)
__device__ float g_ck[KK];
__device__ float g_rm[128], g_rs[128];

// ---------------- common helpers ----------------
__device__ __forceinline__ unsigned smem_u32(const void* p) {
    unsigned r;
    asm("{ .reg .u64 t; cvta.to.shared.u64 t, %1; cvt.u32.u64 %0, t; }" : "=r"(r) : "l"(p));
    return r;
}
#define MBAR_INIT(addr, cnt) \
    asm volatile("mbarrier.init.shared.b64 [%0], %1;" :: "r"(addr), "r"(cnt) : "memory")
#define MBAR_EXPECT_TX(addr, bytes) \
    asm volatile("mbarrier.arrive.expect_tx.shared.b64 _, [%0], %1;" :: "r"(addr), "r"(bytes) : "memory")
#define MBAR_ARRIVE(addr) \
    asm volatile("mbarrier.arrive.shared.b64 _, [%0];" :: "r"(addr) : "memory")
#define MBAR_WAIT(addr, parity) \
    asm volatile("{\n\t.reg .pred P;\n\tWL_%=:\n\t" \
        "mbarrier.try_wait.parity.acquire.cta.shared::cta.b64 P, [%0], %1, 0x989680;\n\t" \
        "@P bra.uni WD_%=;\n\tbra.uni WL_%=;\n\tWD_%=:\n\t}" \
        :: "r"(addr), "r"(parity) : "memory")
#define BULK_CP(dst, src, bytes, bar) \
    asm volatile("cp.async.bulk.shared::cluster.global.mbarrier::complete_tx::bytes [%0], [%1], %2, [%3];" \
        :: "r"(dst), "l"(src), "r"(bytes), "r"(bar) : "memory")

#if USE_TC
// ---------------- tcgen05 helpers (sm_103a-only) ----------------
#define T_ALLOC(smaddr, n) \
    asm volatile("tcgen05.alloc.cta_group::1.sync.aligned.shared::cta.b32 [%0], %1;" :: "r"(smaddr), "r"(n) : "memory")
#define T_DEALLOC(t, n) \
    asm volatile("tcgen05.dealloc.cta_group::1.sync.aligned.b32 %0, %1;" :: "r"(t), "r"(n))
#define T_COMMIT(bar) \
    asm volatile("tcgen05.commit.cta_group::1.mbarrier::arrive::one.shared::cluster.b64 [%0];" :: "r"(bar) : "memory")
#define T_FENCE_AFTER()  asm volatile("tcgen05.fence::after_thread_sync;" ::: "memory")
#define T_FENCE_BEFORE() asm volatile("tcgen05.fence::before_thread_sync;" ::: "memory")
#define T_WAIT_LD()      asm volatile("tcgen05.wait::ld.sync.aligned;" ::: "memory")
#define T_WAIT_ST()      asm volatile("tcgen05.wait::st.sync.aligned;" ::: "memory")

#define T_LD_X32(r, tmem_addr) \
    asm volatile( \
        "tcgen05.ld.sync.aligned.32x32b.x32.b32 " \
        "{%0, %1, %2, %3, %4, %5, %6, %7, " \
        " %8, %9, %10, %11, %12, %13, %14, %15, " \
        " %16, %17, %18, %19, %20, %21, %22, %23, " \
        " %24, %25, %26, %27, %28, %29, %30, %31}, [%32];" \
        : "=r"((r)[0]),  "=r"((r)[1]),  "=r"((r)[2]),  "=r"((r)[3]), \
          "=r"((r)[4]),  "=r"((r)[5]),  "=r"((r)[6]),  "=r"((r)[7]), \
          "=r"((r)[8]),  "=r"((r)[9]),  "=r"((r)[10]), "=r"((r)[11]), \
          "=r"((r)[12]), "=r"((r)[13]), "=r"((r)[14]), "=r"((r)[15]), \
          "=r"((r)[16]), "=r"((r)[17]), "=r"((r)[18]), "=r"((r)[19]), \
          "=r"((r)[20]), "=r"((r)[21]), "=r"((r)[22]), "=r"((r)[23]), \
          "=r"((r)[24]), "=r"((r)[25]), "=r"((r)[26]), "=r"((r)[27]), \
          "=r"((r)[28]), "=r"((r)[29]), "=r"((r)[30]), "=r"((r)[31]) \
        : "r"(tmem_addr))

#define T_ST_X32(tmem_addr, r) \
    asm volatile( \
        "tcgen05.st.sync.aligned.32x32b.x32.b32 [%0], " \
        "{%1, %2, %3, %4, %5, %6, %7, %8, " \
        " %9, %10, %11, %12, %13, %14, %15, %16, " \
        " %17, %18, %19, %20, %21, %22, %23, %24, " \
        " %25, %26, %27, %28, %29, %30, %31, %32};" \
        :: "r"(tmem_addr), \
           "r"((r)[0]),  "r"((r)[1]),  "r"((r)[2]),  "r"((r)[3]), \
           "r"((r)[4]),  "r"((r)[5]),  "r"((r)[6]),  "r"((r)[7]), \
           "r"((r)[8]),  "r"((r)[9]),  "r"((r)[10]), "r"((r)[11]), \
           "r"((r)[12]), "r"((r)[13]), "r"((r)[14]), "r"((r)[15]), \
           "r"((r)[16]), "r"((r)[17]), "r"((r)[18]), "r"((r)[19]), \
           "r"((r)[20]), "r"((r)[21]), "r"((r)[22]), "r"((r)[23]), \
           "r"((r)[24]), "r"((r)[25]), "r"((r)[26]), "r"((r)[27]), \
           "r"((r)[28]), "r"((r)[29]), "r"((r)[30]), "r"((r)[31]) \
        : "memory")

#define T_ST_X8(tmem_addr, r) \
    asm volatile( \
        "tcgen05.st.sync.aligned.32x32b.x8.b32 [%0], " \
        "{%1, %2, %3, %4, %5, %6, %7, %8};" \
        :: "r"(tmem_addr), \
           "r"((r)[0]), "r"((r)[1]), "r"((r)[2]), "r"((r)[3]), \
           "r"((r)[4]), "r"((r)[5]), "r"((r)[6]), "r"((r)[7]) \
        : "memory")

// SW128 K-major smem descriptor (verified layout)
__device__ __forceinline__ uint64_t make_desc(uint32_t addr) {
    const uint64_t base = (uint64_t(2) << 61) | (uint64_t(1) << 46) |
                          (uint64_t(64) << 32) | (uint64_t(1) << 16);
    return base | ((uint64_t)(addr >> 4) & 0x3FFF);
}

// cg1 bf16 TS MMA (A in TMEM): idesc dtype F32, a/b BF16, N=64, M=128
#define MMA_IDESC 0x8100490u
__device__ __forceinline__ void mma_f16_ts(uint32_t d, uint32_t a, uint64_t b, uint32_t en) {
    asm volatile(
        "{\n\t.reg .pred p;\n\tsetp.ne.u32 p, %4, 0;\n\t"
        "tcgen05.mma.cta_group::1.kind::f16 [%0], [%1], %2, %3, {%5, %5, %5, %5}, p;\n\t}"
        :: "r"(d), "r"(a), "l"(b), "r"(MMA_IDESC), "r"(en), "r"(0u) : "memory");
}

// 15 K-steps, K=80: (Ahi,Bhi)x5 + (Alo,Bhi)x5 + (Ahi,Blo)x5
__device__ __forceinline__ void issue_mma_k(uint32_t dtm, uint32_t ahi, uint32_t alo, uint64_t bhi) {
    const int acol[5] = {0, 8, 16, 24, 32};
    const int boff[5] = {0, 2, 4, 6, 512};
    uint64_t blo = bhi + 1024;                // lo half at +16384B
    uint32_t en = 0;
#pragma unroll
    for (int s = 0; s < 5; s++) { mma_f16_ts(dtm, ahi + acol[s], bhi + boff[s], en); en = 1; }
#pragma unroll
    for (int s = 0; s < 5; s++) mma_f16_ts(dtm, alo + acol[s], bhi + boff[s], 1);
#pragma unroll
    for (int s = 0; s < 5; s++) mma_f16_ts(dtm, ahi + acol[s], blo + boff[s], 1);
}
#endif  // USE_TC

// ============= setup v3: Sigma -> in-place rank-2 Gauss-Jordan inverse -> pack =============
// maha' = x^T Sinv x - 2 b^T x via MMA; logdet = sum log det(2x2 pivots)
extern __shared__ float dsm[];
__global__ void __launch_bounds__(256) setup_kernel(const float* __restrict__ L,
                                                    const float* __restrict__ mu,
                                                    const float* __restrict__ w) {
    float* Lt = dsm;                 // [64][65]: L^T
    float* A  = dsm + 64 * 65;       // [64][65]: Sigma -> Sinv (in place)
    __shared__ float rb0[64], rb1[64], cb0[64], cb1[64];
    __shared__ float qv[4];          // 2x2 pivot inverse
    __shared__ float pivd[32];       // det of each 2x2 pivot
    __shared__ float bvec[64], colmu[64];
    int k = blockIdx.x, tid = threadIdx.x;

    // load L transposed: Lt[m][d] = L[k][d][m]
    for (int i = tid; i < DD * DD; i += 256) {
        int d = i >> 6, m = i & 63;
        Lt[m * 65 + d] = L[(size_t)k * DD * DD + i];
    }
    __syncthreads();

    // Sigma = tril(L) tril(L)^T + I (compute lower, mirror to upper)
    for (int i = tid; i < DD * DD; i += 256) {
        int d = i >> 6, e = i & 63;
        if (e <= d) {
            float s = (d == e) ? 1.0f : 0.0f;
            for (int m = 0; m <= e; m++) s = fmaf(Lt[m * 65 + d], Lt[m * 65 + e], s);
            A[d * 65 + e] = s;
            if (e < d) A[e * 65 + d] = s;
        }
    }
    __syncthreads();

    // ---- in-place rank-2 Gauss-Jordan inversion (PD, no pivot search) ----
#pragma unroll 1
    for (int s = 0; s < 32; s++) {
        int j = 2 * s;
        // snapshot pivot rows/cols + compute 2x2 inverse
        if (tid < 64) { rb0[tid] = A[j * 65 + tid]; rb1[tid] = A[(j + 1) * 65 + tid]; }
        else if (tid < 128) {
            int i2 = tid - 64;
            cb0[i2] = A[i2 * 65 + j];
            cb1[i2] = A[i2 * 65 + j + 1];
        } else if (tid == 128) {
            float a00 = A[j * 65 + j],       a01 = A[j * 65 + j + 1];
            float a10 = A[(j + 1) * 65 + j], a11 = A[(j + 1) * 65 + j + 1];
            float det = a00 * a11 - a01 * a10;
            float id = 1.0f / det;
            qv[0] = a11 * id;  qv[1] = -a01 * id;
            qv[2] = -a10 * id; qv[3] = a00 * id;
            pivd[s] = det;
        }
        __syncthreads();
        float q00 = qv[0], q01 = qv[1], q10 = qv[2], q11 = qv[3];
        int i = tid >> 2, cbase = (tid & 3) * 16;
        float f0 = cb0[i] * q00 + cb1[i] * q10;
        float f1 = cb0[i] * q01 + cb1[i] * q11;
        bool ip = (i == j) || (i == j + 1);
        float qr0 = (i == j) ? q00 : q10;
        float qr1 = (i == j) ? q01 : q11;
#pragma unroll
        for (int cc = 0; cc < 16; cc++) {
            int c = cbase + cc;
            bool cpj = (c == j), cpj1 = (c == j + 1);
            float val;
            if (ip) {
                if (cpj) val = qr0;
                else if (cpj1) val = qr1;
                else val = qr0 * rb0[c] + qr1 * rb1[c];
            } else {
                if (cpj) val = -f0;
                else if (cpj1) val = -f1;
                else val = fmaf(-f0, rb0[c], fmaf(-f1, rb1[c], A[i * 65 + c]));
            }
            A[i * 65 + c] = val;
        }
        __syncthreads();
    }

    // A now = Sinv.  b = Sinv * mu (4 threads per row)
    if (tid < 64) colmu[tid] = mu[k * DD + tid];
    __syncthreads();
    {
        int jr = tid >> 2, s4 = tid & 3;
        float p = 0.f;
        for (int c = s4; c < DD; c += 4) p = fmaf(A[jr * 65 + c], colmu[c], p);
        p += __shfl_xor_sync(0xffffffffu, p, 1, 4);
        p += __shfl_xor_sync(0xffffffffu, p, 2, 4);
        if (s4 == 0) bvec[jr] = p;
    }
    __syncthreads();

    // pack B~ rows = [Sinv row j | -2 b_j | 0...] hi/lo bf16 blocked-atom SW128 + fp32 copy
    for (int idx = tid; idx < 64 * 128; idx += 256) {
        int j = idx >> 7, c = idx & 127;
        float v = 0.f;
        if (c < 64) v = A[j * 65 + c];
        else if (c == 64) v = -2.0f * bvec[j];
        __nv_bfloat16 hi = __float2bfloat16(v);
        __nv_bfloat16 lo = __float2bfloat16(v - __bfloat162float(hi));
        uint32_t byte = (uint32_t)(((j >> 3) + (c >> 6) * 8) * 1024 + (j & 7) * 128 + (c & 63) * 2);
        uint32_t sw = byte ^ ((byte >> 3) & 0x70);
        *(__nv_bfloat16*)(g_Bcat + (size_t)k * 32768 + sw) = hi;
        *(__nv_bfloat16*)(g_Bcat + (size_t)k * 32768 + 16384 + sw) = lo;
        if (c < 68) g_Wf[k][j * 68 + c] = v;
    }
    // ck = log_softmax(w)[k] - 0.5*(D log2pi + logdet + mu.b)
    if (tid < 32) {
        float ldv = logf(pivd[tid]);
        float c2 = bvec[tid] * colmu[tid] + bvec[tid + 32] * colmu[tid + 32];
        for (int o = 16; o; o >>= 1) {
            ldv += __shfl_xor_sync(0xffffffffu, ldv, o);
            c2  += __shfl_xor_sync(0xffffffffu, c2, o);
        }
        float wv = w[tid];
        float mxw = wv;
        for (int o = 16; o; o >>= 1) mxw = fmaxf(mxw, __shfl_xor_sync(0xffffffffu, mxw, o));
        float se = __expf(wv - mxw);
        for (int o = 16; o; o >>= 1) se += __shfl_xor_sync(0xffffffffu, se, o);
        float lgk = __shfl_sync(0xffffffffu, wv - (mxw + logf(se)), k);
        if (tid == 0) g_ck[k] = lgk - 0.5f * (DD * LOG_2PI + ldv + c2);
    }
}

// ============= main: 256 points/CTA (2 MMA tiles), warp-specialized producer =============
// TMEM (alloc 512): A0hi 0..39, A0lo 40..79, A1hi 80..119, A1lo 120..159,
//                   D(g,b) = 160 + g*128 + b*64
// dyn smem: 3 x 32KB B ring (+1KB align)
// barriers: s_bar[0,1]=mma_done(cnt 1), [2,3]=cons(cnt 8), [4,5,6]=bfull(cnt 1)
__global__ void __launch_bounds__(288, 1) main_kernel(const float* __restrict__ X) {
#if USE_TC
    extern __shared__ char msm[];
    __shared__ unsigned long long s_bar[7];
    __shared__ uint32_t s_tmem;
    __shared__ float s_ck[KK];
    __shared__ float s_wm[9], s_ws[9];

    uint32_t raw = smem_u32(msm);
    uint32_t sbase = (raw + 1023u) & ~1023u;
    int tx = threadIdx.x, wid = tx >> 5, lane = tx & 31;

    if (wid == 0) T_ALLOC(smem_u32(&s_tmem), 512);
    if (tx == 0) {
        MBAR_INIT(smem_u32(&s_bar[0]), 1);
        MBAR_INIT(smem_u32(&s_bar[1]), 1);
        MBAR_INIT(smem_u32(&s_bar[2]), 8);
        MBAR_INIT(smem_u32(&s_bar[3]), 8);
        MBAR_INIT(smem_u32(&s_bar[4]), 1);
        MBAR_INIT(smem_u32(&s_bar[5]), 1);
        MBAR_INIT(smem_u32(&s_bar[6]), 1);
    }
    if (tx < KK) s_ck[tx] = g_ck[tx];
    __syncthreads();

    uint32_t tmem;
    asm volatile("ld.shared.b32 %0, [%1];" : "=r"(tmem) : "r"(smem_u32(&s_tmem)));

    // producer: kick off B ring prologue copies (k=0,1,2) immediately
    if (tx == 256) {
#pragma unroll
        for (int q = 0; q < 3; q++) {
            unsigned bf = smem_u32(&s_bar[4 + q]);
            MBAR_EXPECT_TX(bf, 32768u);
            BULK_CP(sbase + q * 32768u, g_Bcat + (size_t)q * 32768u, 32768u, bf);
        }
    }

    // consumers: keep x in fp32 regs + build A (both tiles) in TMEM
    float xf[64];
    if (tx < 256) {
        int g = tx >> 7, gtx = tx & 127;
        const float4* xs = (const float4*)(X + ((size_t)blockIdx.x * 256 + g * 128 + gtx) * DD);
        uint32_t warp_off = (uint32_t)((gtx >> 5) << 21);
        uint32_t h[40], l[40];
#pragma unroll
        for (int i = 0; i < 16; i++) {
            float4 v = xs[i];
            xf[4 * i] = v.x; xf[4 * i + 1] = v.y; xf[4 * i + 2] = v.z; xf[4 * i + 3] = v.w;
            __nv_bfloat162 hp0, hp1, lp0, lp1;
            hp0.x = __float2bfloat16(v.x); hp0.y = __float2bfloat16(v.y);
            hp1.x = __float2bfloat16(v.z); hp1.y = __float2bfloat16(v.w);
            lp0.x = __float2bfloat16(v.x - __bfloat162float(hp0.x));
            lp0.y = __float2bfloat16(v.y - __bfloat162float(hp0.y));
            lp1.x = __float2bfloat16(v.z - __bfloat162float(hp1.x));
            lp1.y = __float2bfloat16(v.w - __bfloat162float(hp1.y));
            h[2 * i]     = *(uint32_t*)&hp0;
            h[2 * i + 1] = *(uint32_t*)&hp1;
            l[2 * i]     = *(uint32_t*)&lp0;
            l[2 * i + 1] = *(uint32_t*)&lp1;
        }
        {
            __nv_bfloat162 one; one.x = __float2bfloat16(1.0f); one.y = __float2bfloat16(0.0f);
            h[32] = *(uint32_t*)&one;
            l[32] = 0u;
#pragma unroll
            for (int i = 33; i < 40; i++) { h[i] = 0u; l[i] = 0u; }
        }
        uint32_t abase = tmem + (uint32_t)(g * 80);
        T_ST_X32(abase + 0 + warp_off, h);
        T_ST_X8(abase + 32 + warp_off, h + 32);
        T_ST_X32(abase + 40 + warp_off, l);
        T_ST_X8(abase + 72 + warp_off, l + 32);
        T_WAIT_ST();
        T_FENCE_BEFORE();
    }
    __syncthreads();    // A ready in TMEM for producer's MMAs

    // ---------------- producer warp: MMA issue + B prefetch ----------------
    if (tx == 256) {
        T_FENCE_AFTER();
#pragma unroll 1
        for (int k = 0; k < KK; k++) {
            int b = k & 1;
            int q = k - (k / 3) * 3;
            MBAR_WAIT(smem_u32(&s_bar[4 + q]), (k / 3) & 1);             // B(k) in smem
            if (k >= 2) MBAR_WAIT(smem_u32(&s_bar[2 + b]), ((k - 2) >> 1) & 1);  // D[b] free
            uint64_t bd = make_desc(sbase + q * 32768u);
            issue_mma_k(tmem + 160 + b * 64, tmem + 0,  tmem + 40,  bd);  // tile 0
            issue_mma_k(tmem + 288 + b * 64, tmem + 80, tmem + 120, bd);  // tile 1
            T_COMMIT(smem_u32(&s_bar[b]));
            if (k + 3 < KK) {
                MBAR_WAIT(smem_u32(&s_bar[b]), (k >> 1) & 1);            // MMA(k) done -> B[q] free
                unsigned bf = smem_u32(&s_bar[4 + q]);
                MBAR_EXPECT_TX(bf, 32768u);
                BULK_CP(sbase + q * 32768u, g_Bcat + (size_t)(k + 3) * 32768u, 32768u, bf);
            }
        }
    }

    // ---------------- consumer warps: dot-product epilogue + online LSE ----------------
    float mx = -INFINITY, sm = 0.f;
    if (tx < 256) {
        int g = tx >> 7;
        uint32_t dbase = tmem + 160 + (uint32_t)(g * 128);
#pragma unroll 1
        for (int k = 0; k < KK; k++) {
            int b = k & 1;
            MBAR_WAIT(smem_u32(&s_bar[b]), (k >> 1) & 1);
            T_FENCE_AFTER();
            uint32_t dr[64];
            T_LD_X32(dr, dbase + b * 64);
            T_LD_X32(dr + 32, dbase + b * 64 + 32);
            T_WAIT_LD();
            if (lane == 0) MBAR_ARRIVE(smem_u32(&s_bar[2 + b]));   // D reads retired
            // maha' = sum_j x_j * z_j  (z = Sinv x - 2b)
            float m0 = 0.f, m1 = 0.f, m2 = 0.f, m3 = 0.f;
#pragma unroll
            for (int j = 0; j < 16; j++) {
                m0 = fmaf(xf[4 * j],     __uint_as_float(dr[4 * j]),     m0);
                m1 = fmaf(xf[4 * j + 1], __uint_as_float(dr[4 * j + 1]), m1);
                m2 = fmaf(xf[4 * j + 2], __uint_as_float(dr[4 * j + 2]), m2);
                m3 = fmaf(xf[4 * j + 3], __uint_as_float(dr[4 * j + 3]), m3);
            }
            float logp = s_ck[k] - 0.5f * ((m0 + m1) + (m2 + m3));
            if (logp > mx) { sm = fmaf(sm, __expf(mx - logp), 1.0f); mx = logp; }
            else           { sm += __expf(logp - mx); }
        }
    }

    // block LSE reduce -> per-CTA (M, S)
    if (tx < 256) {
#pragma unroll
        for (int o = 16; o; o >>= 1) {
            float m2 = __shfl_xor_sync(0xffffffffu, mx, o);
            float s2 = __shfl_xor_sync(0xffffffffu, sm, o);
            float M = fmaxf(mx, m2);
            sm = sm * __expf(mx - M) + s2 * __expf(m2 - M);
            mx = M;
        }
        if (lane == 0) { s_wm[wid] = mx; s_ws[wid] = sm; }
    }
    __syncthreads();
    if (tx < 8) {
        float m = s_wm[tx], s = s_ws[tx];
#pragma unroll
        for (int o = 4; o; o >>= 1) {
            float m2 = __shfl_xor_sync(0xffu, m, o);
            float s2 = __shfl_xor_sync(0xffu, s, o);
            float M = fmaxf(m, m2);
            s = s * __expf(m - M) + s2 * __expf(m2 - M);
            m = M;
        }
        if (tx == 0) { g_rm[blockIdx.x] = m; g_rs[blockIdx.x] = s; }
    }
    __syncthreads();
    if (wid == 0) T_DEALLOC(tmem, 512);
#else
    // ---------- generic scalar fallback: maha' = x . (B~ x~) ----------
    extern __shared__ char msm[];
    float* sW = (float*)msm;                  // [64*68] fp32 B~ for current k
    __shared__ float s_ck[KK];
    __shared__ float s_wm[9], s_ws[9];
    int tx = threadIdx.x, wid = tx >> 5, lane = tx & 31;
    if (tx < KK) s_ck[tx] = g_ck[tx];

    float xt[65];
    if (tx < 256) {
        const float4* xs = (const float4*)(X + ((size_t)blockIdx.x * 256 + tx) * DD);
#pragma unroll
        for (int i = 0; i < 16; i++) {
            float4 v = xs[i];
            xt[4 * i] = v.x; xt[4 * i + 1] = v.y; xt[4 * i + 2] = v.z; xt[4 * i + 3] = v.w;
        }
        xt[64] = 1.0f;
    }

    float mx = -INFINITY, sm = 0.f;
#pragma unroll 1
    for (int k = 0; k < KK; k++) {
        __syncthreads();
        const float4* src = (const float4*)g_Wf[k];
        for (int i = tx; i < 64 * 68 / 4; i += 288) ((float4*)sW)[i] = src[i];
        __syncthreads();
        if (tx < 256) {
            float maha = 0.f;
            for (int j = 0; j < 64; j++) {
                const float* row = sW + j * 68;
                float z = 0.f;
#pragma unroll
                for (int c = 0; c < 65; c++) z = fmaf(row[c], xt[c], z);
                maha = fmaf(xt[j], z, maha);
            }
            float logp = s_ck[k] - 0.5f * maha;
            if (logp > mx) { sm = fmaf(sm, __expf(mx - logp), 1.0f); mx = logp; }
            else           { sm += __expf(logp - mx); }
        }
    }
    if (tx < 256) {
#pragma unroll
        for (int o = 16; o; o >>= 1) {
            float m2 = __shfl_xor_sync(0xffffffffu, mx, o);
            float s2 = __shfl_xor_sync(0xffffffffu, sm, o);
            float M = fmaxf(mx, m2);
            sm = sm * __expf(mx - M) + s2 * __expf(m2 - M);
            mx = M;
        }
        if (lane == 0) { s_wm[wid] = mx; s_ws[wid] = sm; }
    }
    __syncthreads();
    if (tx < 8) {
        float m = s_wm[tx], s = s_ws[tx];
#pragma unroll
        for (int o = 4; o; o >>= 1) {
            float m2 = __shfl_xor_sync(0xffu, m, o);
            float s2 = __shfl_xor_sync(0xffu, s, o);
            float M = fmaxf(m, m2);
            s = s * __expf(m - M) + s2 * __expf(m2 - M);
            m = M;
        }
        if (tx == 0) { g_rm[blockIdx.x] = m; g_rs[blockIdx.x] = s; }
    }
#endif
}

// ============= final reduce: -logsumexp over 128 CTA partials =============
__global__ void reduce_kernel(float* __restrict__ out) {
    __shared__ float rm[4], rs[4];
    int tx = threadIdx.x, lane = tx & 31, wid = tx >> 5;
    float m = g_rm[tx], s = g_rs[tx];
#pragma unroll
    for (int o = 16; o; o >>= 1) {
        float m2 = __shfl_xor_sync(0xffffffffu, m, o);
        float s2 = __shfl_xor_sync(0xffffffffu, s, o);
        float M = fmaxf(m, m2);
        s = s * __expf(m - M) + s2 * __expf(m2 - M);
        m = M;
    }
    if (lane == 0) { rm[wid] = m; rs[wid] = s; }
    __syncthreads();
    if (tx < 4) {
        float mm = rm[tx], ss = rs[tx];
#pragma unroll
        for (int o = 2; o; o >>= 1) {
            float m2 = __shfl_xor_sync(0xfu, mm, o);
            float s2 = __shfl_xor_sync(0xfu, ss, o);
            float M = fmaxf(mm, m2);
            ss = ss * __expf(mm - M) + s2 * __expf(m2 - M);
            mm = M;
        }
        if (tx == 0) out[0] = -(mm + logf(ss));
    }
}

// ---------------- launch ----------------
extern "C" void kernel_launch(void* const* d_in, const int* in_sizes, int n_in,
                              void* d_out, int out_size) {
    const float* X  = (const float*)d_in[0];
    const float* mu = (const float*)d_in[1];
    const float* L  = (const float*)d_in[2];
    const float* w  = (const float*)d_in[3];
    float* out = (float*)d_out;

    static int attr_done = 0;
    if (!attr_done) {
        cudaFuncSetAttribute(setup_kernel, cudaFuncAttributeMaxDynamicSharedMemorySize, 33280);
        cudaFuncSetAttribute(main_kernel, cudaFuncAttributeMaxDynamicSharedMemorySize, 99328);
        attr_done = 1;
    }

    setup_kernel<<<KK, 256, 33280>>>(L, mu, w);
    main_kernel<<<NPTS / 256, 288, 99328>>>(X);
    reduce_kernel<<<1, 128>>>(out);
}

// round 17
// speedup vs baseline: 3.2677x; 1.3764x over previous
#include <cuda_runtime.h>
#include <cuda_bf16.h>
#include <math.h>
#include <stdint.h>

#define NPTS 32768
#define KK 32
#define DD 64
#define LOG_2PI 1.8378770664093453f

// tcgen05 is arch-SPECIFIC (sm_103a). The harness also builds a plain
// compute_103 PTX pass, which must not see tcgen05 instructions.
#if defined(__CUDA_ARCH__) && (defined(__CUDA_ARCH_FEAT_SM103_ALL) || \
    defined(__CUDA_ARCH_FEAT_SM100_ALL) || defined(__CUDA_ARCH_FEAT_SM101_ALL) || \
    defined(__CUDA_ARCH_FEAT_SM110_ALL) || defined(__CUDA_ARCH_FEAT_SM120_ALL))
#define USE_TC 1
#else
#define USE_TC 0
#endif

// ---------------- device scratch ----------------
// per-k B tile: [hi 16KB][lo 16KB]; each = 64 rows x 128 K-cols bf16,
// blocked SW128 atoms (8 rows x 64 bf16 = 1024B; atom_off = arow + acol*8)
// row j of B~ = [Sinv row j | -2*b_j | 0...], b = Sinv*mu
__device__ __align__(16) unsigned char g_Bcat[KK * 32768];
__device__ __align__(16) float g_Wf[KK][64 * 68];   // fp32 B~ rows (fallback path)
__device__ float g_ck[KK];
__device__ float g_rm[128], g_rs[128];

// ---------------- common helpers ----------------
__device__ __forceinline__ unsigned smem_u32(const void* p) {
    unsigned r;
    asm("{ .reg .u64 t; cvta.to.shared.u64 t, %1; cvt.u32.u64 %0, t; }" : "=r"(r) : "l"(p));
    return r;
}
#define MBAR_INIT(addr, cnt) \
    asm volatile("mbarrier.init.shared.b64 [%0], %1;" :: "r"(addr), "r"(cnt) : "memory")
#define MBAR_EXPECT_TX(addr, bytes) \
    asm volatile("mbarrier.arrive.expect_tx.shared.b64 _, [%0], %1;" :: "r"(addr), "r"(bytes) : "memory")
#define MBAR_ARRIVE(addr) \
    asm volatile("mbarrier.arrive.shared.b64 _, [%0];" :: "r"(addr) : "memory")
#define MBAR_WAIT(addr, parity) \
    asm volatile("{\n\t.reg .pred P;\n\tWL_%=:\n\t" \
        "mbarrier.try_wait.parity.acquire.cta.shared::cta.b64 P, [%0], %1, 0x989680;\n\t" \
        "@P bra.uni WD_%=;\n\tbra.uni WL_%=;\n\tWD_%=:\n\t}" \
        :: "r"(addr), "r"(parity) : "memory")
#define BULK_CP(dst, src, bytes, bar) \
    asm volatile("cp.async.bulk.shared::cluster.global.mbarrier::complete_tx::bytes [%0], [%1], %2, [%3];" \
        :: "r"(dst), "l"(src), "r"(bytes), "r"(bar) : "memory")

#if USE_TC
// ---------------- tcgen05 helpers (sm_103a-only) ----------------
#define T_ALLOC(smaddr, n) \
    asm volatile("tcgen05.alloc.cta_group::1.sync.aligned.shared::cta.b32 [%0], %1;" :: "r"(smaddr), "r"(n) : "memory")
#define T_DEALLOC(t, n) \
    asm volatile("tcgen05.dealloc.cta_group::1.sync.aligned.b32 %0, %1;" :: "r"(t), "r"(n))
#define T_COMMIT(bar) \
    asm volatile("tcgen05.commit.cta_group::1.mbarrier::arrive::one.shared::cluster.b64 [%0];" :: "r"(bar) : "memory")
#define T_FENCE_AFTER()  asm volatile("tcgen05.fence::after_thread_sync;" ::: "memory")
#define T_FENCE_BEFORE() asm volatile("tcgen05.fence::before_thread_sync;" ::: "memory")
#define T_WAIT_LD()      asm volatile("tcgen05.wait::ld.sync.aligned;" ::: "memory")
#define T_WAIT_ST()      asm volatile("tcgen05.wait::st.sync.aligned;" ::: "memory")

#define T_LD_X32(r, tmem_addr) \
    asm volatile( \
        "tcgen05.ld.sync.aligned.32x32b.x32.b32 " \
        "{%0, %1, %2, %3, %4, %5, %6, %7, " \
        " %8, %9, %10, %11, %12, %13, %14, %15, " \
        " %16, %17, %18, %19, %20, %21, %22, %23, " \
        " %24, %25, %26, %27, %28, %29, %30, %31}, [%32];" \
        : "=r"((r)[0]),  "=r"((r)[1]),  "=r"((r)[2]),  "=r"((r)[3]), \
          "=r"((r)[4]),  "=r"((r)[5]),  "=r"((r)[6]),  "=r"((r)[7]), \
          "=r"((r)[8]),  "=r"((r)[9]),  "=r"((r)[10]), "=r"((r)[11]), \
          "=r"((r)[12]), "=r"((r)[13]), "=r"((r)[14]), "=r"((r)[15]), \
          "=r"((r)[16]), "=r"((r)[17]), "=r"((r)[18]), "=r"((r)[19]), \
          "=r"((r)[20]), "=r"((r)[21]), "=r"((r)[22]), "=r"((r)[23]), \
          "=r"((r)[24]), "=r"((r)[25]), "=r"((r)[26]), "=r"((r)[27]), \
          "=r"((r)[28]), "=r"((r)[29]), "=r"((r)[30]), "=r"((r)[31]) \
        : "r"(tmem_addr))

#define T_ST_X32(tmem_addr, r) \
    asm volatile( \
        "tcgen05.st.sync.aligned.32x32b.x32.b32 [%0], " \
        "{%1, %2, %3, %4, %5, %6, %7, %8, " \
        " %9, %10, %11, %12, %13, %14, %15, %16, " \
        " %17, %18, %19, %20, %21, %22, %23, %24, " \
        " %25, %26, %27, %28, %29, %30, %31, %32};" \
        :: "r"(tmem_addr), \
           "r"((r)[0]),  "r"((r)[1]),  "r"((r)[2]),  "r"((r)[3]), \
           "r"((r)[4]),  "r"((r)[5]),  "r"((r)[6]),  "r"((r)[7]), \
           "r"((r)[8]),  "r"((r)[9]),  "r"((r)[10]), "r"((r)[11]), \
           "r"((r)[12]), "r"((r)[13]), "r"((r)[14]), "r"((r)[15]), \
           "r"((r)[16]), "r"((r)[17]), "r"((r)[18]), "r"((r)[19]), \
           "r"((r)[20]), "r"((r)[21]), "r"((r)[22]), "r"((r)[23]), \
           "r"((r)[24]), "r"((r)[25]), "r"((r)[26]), "r"((r)[27]), \
           "r"((r)[28]), "r"((r)[29]), "r"((r)[30]), "r"((r)[31]) \
        : "memory")

#define T_ST_X8(tmem_addr, r) \
    asm volatile( \
        "tcgen05.st.sync.aligned.32x32b.x8.b32 [%0], " \
        "{%1, %2, %3, %4, %5, %6, %7, %8};" \
        :: "r"(tmem_addr), \
           "r"((r)[0]), "r"((r)[1]), "r"((r)[2]), "r"((r)[3]), \
           "r"((r)[4]), "r"((r)[5]), "r"((r)[6]), "r"((r)[7]) \
        : "memory")

// SW128 K-major smem descriptor (verified layout)
__device__ __forceinline__ uint64_t make_desc(uint32_t addr) {
    const uint64_t base = (uint64_t(2) << 61) | (uint64_t(1) << 46) |
                          (uint64_t(64) << 32) | (uint64_t(1) << 16);
    return base | ((uint64_t)(addr >> 4) & 0x3FFF);
}

// cg1 bf16 TS MMA (A in TMEM): idesc dtype F32, a/b BF16, N=64, M=128
#define MMA_IDESC 0x8100490u
__device__ __forceinline__ void mma_f16_ts(uint32_t d, uint32_t a, uint64_t b, uint32_t en) {
    asm volatile(
        "{\n\t.reg .pred p;\n\tsetp.ne.u32 p, %4, 0;\n\t"
        "tcgen05.mma.cta_group::1.kind::f16 [%0], [%1], %2, %3, {%5, %5, %5, %5}, p;\n\t}"
        :: "r"(d), "r"(a), "l"(b), "r"(MMA_IDESC), "r"(en), "r"(0u) : "memory");
}

// 15 K-steps, K=80: (Ahi,Bhi)x5 + (Alo,Bhi)x5 + (Ahi,Blo)x5
__device__ __forceinline__ void issue_mma_k(uint32_t dtm, uint32_t ahi, uint32_t alo, uint64_t bhi) {
    const int acol[5] = {0, 8, 16, 24, 32};
    const int boff[5] = {0, 2, 4, 6, 512};
    uint64_t blo = bhi + 1024;                // lo half at +16384B
    uint32_t en = 0;
#pragma unroll
    for (int s = 0; s < 5; s++) { mma_f16_ts(dtm, ahi + acol[s], bhi + boff[s], en); en = 1; }
#pragma unroll
    for (int s = 0; s < 5; s++) mma_f16_ts(dtm, alo + acol[s], bhi + boff[s], 1);
#pragma unroll
    for (int s = 0; s < 5; s++) mma_f16_ts(dtm, ahi + acol[s], blo + boff[s], 1);
}
#endif  // USE_TC

// ============= setup v4: 1024 threads, float4 rank-2 Gauss-Jordan =============
// maha' = x^T Sinv x - 2 b^T x via MMA; logdet = sum log det(2x2 pivots)
// smem: Lt [64][65] (16640 B) then A [64][68] (17408 B), A rows 16B-aligned
#define AST 68
extern __shared__ float dsm[];
__global__ void __launch_bounds__(1024) setup_kernel(const float* __restrict__ L,
                                                     const float* __restrict__ mu,
                                                     const float* __restrict__ w) {
    float* Lt = dsm;                 // [64][65]
    float* A  = dsm + 64 * 65;       // [64][AST]
    __shared__ __align__(16) float rb0[64], rb1[64];
    __shared__ float cb0[64], cb1[64];
    __shared__ float qv[4];          // 2x2 pivot inverse
    __shared__ float pivd[32];       // det of each 2x2 pivot
    __shared__ float bvec[64], colmu[64];
    int k = blockIdx.x, tid = threadIdx.x;

    // load L transposed: Lt[m][d] = L[k][d][m]
    for (int i = tid; i < DD * DD; i += 1024) {
        int d = i >> 6, m = i & 63;
        Lt[m * 65 + d] = L[(size_t)k * DD * DD + i];
    }
    __syncthreads();

    // Sigma = tril(L) tril(L)^T + I (compute lower, mirror to upper)
    for (int i = tid; i < DD * DD; i += 1024) {
        int d = i >> 6, e = i & 63;
        if (e <= d) {
            float s = (d == e) ? 1.0f : 0.0f;
            for (int m = 0; m <= e; m++) s = fmaf(Lt[m * 65 + d], Lt[m * 65 + e], s);
            A[d * AST + e] = s;
            if (e < d) A[e * AST + d] = s;
        }
    }
    __syncthreads();

    // ---- in-place rank-2 Gauss-Jordan inversion (PD, no pivot search) ----
    // 1024 threads: row i = tid>>4, float4 col group grp = tid&15
    int ui = tid >> 4, ugrp = tid & 15;
#pragma unroll 1
    for (int s = 0; s < 32; s++) {
        int j = 2 * s;
        // snapshot pivot rows/cols + 2x2 inverse (parallel across thread ranges)
        if (tid < 64) rb0[tid] = A[j * AST + tid];
        else if (tid < 128) rb1[tid - 64] = A[(j + 1) * AST + (tid - 64)];
        else if (tid < 192) cb0[tid - 128] = A[(tid - 128) * AST + j];
        else if (tid < 256) cb1[tid - 192] = A[(tid - 192) * AST + j + 1];
        else if (tid == 256) {
            float a00 = A[j * AST + j],       a01 = A[j * AST + j + 1];
            float a10 = A[(j + 1) * AST + j], a11 = A[(j + 1) * AST + j + 1];
            float det = a00 * a11 - a01 * a10;
            float id = 1.0f / det;
            qv[0] = a11 * id;  qv[1] = -a01 * id;
            qv[2] = -a10 * id; qv[3] = a00 * id;
            pivd[s] = det;
        }
        __syncthreads();
        {
            float q00 = qv[0], q01 = qv[1], q10 = qv[2], q11 = qv[3];
            float f0 = cb0[ui] * q00 + cb1[ui] * q10;
            float f1 = cb0[ui] * q01 + cb1[ui] * q11;
            bool ip = (ui == j) || (ui == j + 1);
            float qr0 = (ui == j) ? q00 : q10;
            float qr1 = (ui == j) ? q01 : q11;
            const float4* rb04 = (const float4*)rb0;
            const float4* rb14 = (const float4*)rb1;
            float4* Ar4 = (float4*)(A + ui * AST);
            float4 r0v = rb04[ugrp], r1v = rb14[ugrp];
            float4 av = Ar4[ugrp];
            float4 ov;
            if (ip) {
                ov.x = qr0 * r0v.x + qr1 * r1v.x;
                ov.y = qr0 * r0v.y + qr1 * r1v.y;
                ov.z = qr0 * r0v.z + qr1 * r1v.z;
                ov.w = qr0 * r0v.w + qr1 * r1v.w;
            } else {
                ov.x = fmaf(-f0, r0v.x, fmaf(-f1, r1v.x, av.x));
                ov.y = fmaf(-f0, r0v.y, fmaf(-f1, r1v.y, av.y));
                ov.z = fmaf(-f0, r0v.z, fmaf(-f1, r1v.z, av.z));
                ov.w = fmaf(-f0, r0v.w, fmaf(-f1, r1v.w, av.w));
            }
            if (ugrp == (j >> 2)) {           // pivot-pair cols live in this group
                if ((j & 3) == 0) {
                    ov.x = ip ? qr0 : -f0;
                    ov.y = ip ? qr1 : -f1;
                } else {
                    ov.z = ip ? qr0 : -f0;
                    ov.w = ip ? qr1 : -f1;
                }
            }
            Ar4[ugrp] = ov;
        }
        __syncthreads();
    }

    // A now = Sinv.  b = Sinv * mu (16 threads per row)
    if (tid < 64) colmu[tid] = mu[k * DD + tid];
    __syncthreads();
    {
        int jr = tid >> 4, s16 = tid & 15;
        float p = 0.f;
        for (int c = s16; c < DD; c += 16) p = fmaf(A[jr * AST + c], colmu[c], p);
        p += __shfl_xor_sync(0xffffffffu, p, 1, 16);
        p += __shfl_xor_sync(0xffffffffu, p, 2, 16);
        p += __shfl_xor_sync(0xffffffffu, p, 4, 16);
        p += __shfl_xor_sync(0xffffffffu, p, 8, 16);
        if (s16 == 0) bvec[jr] = p;
    }
    __syncthreads();

    // pack B~ rows = [Sinv row j | -2 b_j | 0...] hi/lo bf16 blocked-atom SW128 + fp32 copy
    for (int idx = tid; idx < 64 * 128; idx += 1024) {
        int j = idx >> 7, c = idx & 127;
        float v = 0.f;
        if (c < 64) v = A[j * AST + c];
        else if (c == 64) v = -2.0f * bvec[j];
        __nv_bfloat16 hi = __float2bfloat16(v);
        __nv_bfloat16 lo = __float2bfloat16(v - __bfloat162float(hi));
        uint32_t byte = (uint32_t)(((j >> 3) + (c >> 6) * 8) * 1024 + (j & 7) * 128 + (c & 63) * 2);
        uint32_t sw = byte ^ ((byte >> 3) & 0x70);
        *(__nv_bfloat16*)(g_Bcat + (size_t)k * 32768 + sw) = hi;
        *(__nv_bfloat16*)(g_Bcat + (size_t)k * 32768 + 16384 + sw) = lo;
        if (c < 68) g_Wf[k][j * 68 + c] = v;
    }
    // ck = log_softmax(w)[k] - 0.5*(D log2pi + logdet + mu.b)
    if (tid < 32) {
        float ldv = logf(pivd[tid]);
        float c2 = bvec[tid] * colmu[tid] + bvec[tid + 32] * colmu[tid + 32];
        for (int o = 16; o; o >>= 1) {
            ldv += __shfl_xor_sync(0xffffffffu, ldv, o);
            c2  += __shfl_xor_sync(0xffffffffu, c2, o);
        }
        float wv = w[tid];
        float mxw = wv;
        for (int o = 16; o; o >>= 1) mxw = fmaxf(mxw, __shfl_xor_sync(0xffffffffu, mxw, o));
        float se = __expf(wv - mxw);
        for (int o = 16; o; o >>= 1) se += __shfl_xor_sync(0xffffffffu, se, o);
        float lgk = __shfl_sync(0xffffffffu, wv - (mxw + logf(se)), k);
        if (tid == 0) g_ck[k] = lgk - 0.5f * (DD * LOG_2PI + ldv + c2);
    }
}

// ============= main: 256 points/CTA (2 MMA tiles), warp-specialized producer =============
// TMEM (alloc 512): A0hi 0..39, A0lo 40..79, A1hi 80..119, A1lo 120..159,
//                   D(g,b) = 160 + g*128 + b*64
// dyn smem: 3 x 32KB B ring (+1KB align)
// barriers: s_bar[0,1]=mma_done(cnt 1), [2,3]=cons(cnt 8), [4,5,6]=bfull(cnt 1)
__global__ void __launch_bounds__(288, 1) main_kernel(const float* __restrict__ X) {
#if USE_TC
    extern __shared__ char msm[];
    __shared__ unsigned long long s_bar[7];
    __shared__ uint32_t s_tmem;
    __shared__ float s_ck[KK];
    __shared__ float s_wm[9], s_ws[9];

    uint32_t raw = smem_u32(msm);
    uint32_t sbase = (raw + 1023u) & ~1023u;
    int tx = threadIdx.x, wid = tx >> 5, lane = tx & 31;

    if (wid == 0) T_ALLOC(smem_u32(&s_tmem), 512);
    if (tx == 0) {
        MBAR_INIT(smem_u32(&s_bar[0]), 1);
        MBAR_INIT(smem_u32(&s_bar[1]), 1);
        MBAR_INIT(smem_u32(&s_bar[2]), 8);
        MBAR_INIT(smem_u32(&s_bar[3]), 8);
        MBAR_INIT(smem_u32(&s_bar[4]), 1);
        MBAR_INIT(smem_u32(&s_bar[5]), 1);
        MBAR_INIT(smem_u32(&s_bar[6]), 1);
    }
    if (tx < KK) s_ck[tx] = g_ck[tx];
    __syncthreads();

    uint32_t tmem;
    asm volatile("ld.shared.b32 %0, [%1];" : "=r"(tmem) : "r"(smem_u32(&s_tmem)));

    // producer: kick off B ring prologue copies (k=0,1,2) immediately
    if (tx == 256) {
#pragma unroll
        for (int q = 0; q < 3; q++) {
            unsigned bf = smem_u32(&s_bar[4 + q]);
            MBAR_EXPECT_TX(bf, 32768u);
            BULK_CP(sbase + q * 32768u, g_Bcat + (size_t)q * 32768u, 32768u, bf);
        }
    }

    // consumers: keep x in fp32 regs + build A (both tiles) in TMEM
    float xf[64];
    if (tx < 256) {
        int g = tx >> 7, gtx = tx & 127;
        const float4* xs = (const float4*)(X + ((size_t)blockIdx.x * 256 + g * 128 + gtx) * DD);
        uint32_t warp_off = (uint32_t)((gtx >> 5) << 21);
        uint32_t h[40], l[40];
#pragma unroll
        for (int i = 0; i < 16; i++) {
            float4 v = xs[i];
            xf[4 * i] = v.x; xf[4 * i + 1] = v.y; xf[4 * i + 2] = v.z; xf[4 * i + 3] = v.w;
            __nv_bfloat162 hp0, hp1, lp0, lp1;
            hp0.x = __float2bfloat16(v.x); hp0.y = __float2bfloat16(v.y);
            hp1.x = __float2bfloat16(v.z); hp1.y = __float2bfloat16(v.w);
            lp0.x = __float2bfloat16(v.x - __bfloat162float(hp0.x));
            lp0.y = __float2bfloat16(v.y - __bfloat162float(hp0.y));
            lp1.x = __float2bfloat16(v.z - __bfloat162float(hp1.x));
            lp1.y = __float2bfloat16(v.w - __bfloat162float(hp1.y));
            h[2 * i]     = *(uint32_t*)&hp0;
            h[2 * i + 1] = *(uint32_t*)&hp1;
            l[2 * i]     = *(uint32_t*)&lp0;
            l[2 * i + 1] = *(uint32_t*)&lp1;
        }
        {
            __nv_bfloat162 one; one.x = __float2bfloat16(1.0f); one.y = __float2bfloat16(0.0f);
            h[32] = *(uint32_t*)&one;
            l[32] = 0u;
#pragma unroll
            for (int i = 33; i < 40; i++) { h[i] = 0u; l[i] = 0u; }
        }
        uint32_t abase = tmem + (uint32_t)(g * 80);
        T_ST_X32(abase + 0 + warp_off, h);
        T_ST_X8(abase + 32 + warp_off, h + 32);
        T_ST_X32(abase + 40 + warp_off, l);
        T_ST_X8(abase + 72 + warp_off, l + 32);
        T_WAIT_ST();
        T_FENCE_BEFORE();
    }
    __syncthreads();    // A ready in TMEM for producer's MMAs

    // ---------------- producer warp: MMA issue + B prefetch ----------------
    if (tx == 256) {
        T_FENCE_AFTER();
#pragma unroll 1
        for (int k = 0; k < KK; k++) {
            int b = k & 1;
            int q = k - (k / 3) * 3;
            MBAR_WAIT(smem_u32(&s_bar[4 + q]), (k / 3) & 1);             // B(k) in smem
            if (k >= 2) MBAR_WAIT(smem_u32(&s_bar[2 + b]), ((k - 2) >> 1) & 1);  // D[b] free
            uint64_t bd = make_desc(sbase + q * 32768u);
            issue_mma_k(tmem + 160 + b * 64, tmem + 0,  tmem + 40,  bd);  // tile 0
            issue_mma_k(tmem + 288 + b * 64, tmem + 80, tmem + 120, bd);  // tile 1
            T_COMMIT(smem_u32(&s_bar[b]));
            if (k + 3 < KK) {
                MBAR_WAIT(smem_u32(&s_bar[b]), (k >> 1) & 1);            // MMA(k) done -> B[q] free
                unsigned bf = smem_u32(&s_bar[4 + q]);
                MBAR_EXPECT_TX(bf, 32768u);
                BULK_CP(sbase + q * 32768u, g_Bcat + (size_t)(k + 3) * 32768u, 32768u, bf);
            }
        }
    }

    // ---------------- consumer warps: dot-product epilogue + online LSE ----------------
    float mx = -INFINITY, sm = 0.f;
    if (tx < 256) {
        int g = tx >> 7;
        uint32_t dbase = tmem + 160 + (uint32_t)(g * 128);
#pragma unroll 1
        for (int k = 0; k < KK; k++) {
            int b = k & 1;
            MBAR_WAIT(smem_u32(&s_bar[b]), (k >> 1) & 1);
            T_FENCE_AFTER();
            uint32_t dr[64];
            T_LD_X32(dr, dbase + b * 64);
            T_LD_X32(dr + 32, dbase + b * 64 + 32);
            T_WAIT_LD();
            if (lane == 0) MBAR_ARRIVE(smem_u32(&s_bar[2 + b]));   // D reads retired
            // maha' = sum_j x_j * z_j  (z = Sinv x - 2b)
            float m0 = 0.f, m1 = 0.f, m2 = 0.f, m3 = 0.f;
#pragma unroll
            for (int j = 0; j < 16; j++) {
                m0 = fmaf(xf[4 * j],     __uint_as_float(dr[4 * j]),     m0);
                m1 = fmaf(xf[4 * j + 1], __uint_as_float(dr[4 * j + 1]), m1);
                m2 = fmaf(xf[4 * j + 2], __uint_as_float(dr[4 * j + 2]), m2);
                m3 = fmaf(xf[4 * j + 3], __uint_as_float(dr[4 * j + 3]), m3);
            }
            float logp = s_ck[k] - 0.5f * ((m0 + m1) + (m2 + m3));
            if (logp > mx) { sm = fmaf(sm, __expf(mx - logp), 1.0f); mx = logp; }
            else           { sm += __expf(logp - mx); }
        }
    }

    // block LSE reduce -> per-CTA (M, S)
    if (tx < 256) {
#pragma unroll
        for (int o = 16; o; o >>= 1) {
            float m2 = __shfl_xor_sync(0xffffffffu, mx, o);
            float s2 = __shfl_xor_sync(0xffffffffu, sm, o);
            float M = fmaxf(mx, m2);
            sm = sm * __expf(mx - M) + s2 * __expf(m2 - M);
            mx = M;
        }
        if (lane == 0) { s_wm[wid] = mx; s_ws[wid] = sm; }
    }
    __syncthreads();
    if (tx < 8) {
        float m = s_wm[tx], s = s_ws[tx];
#pragma unroll
        for (int o = 4; o; o >>= 1) {
            float m2 = __shfl_xor_sync(0xffu, m, o);
            float s2 = __shfl_xor_sync(0xffu, s, o);
            float M = fmaxf(m, m2);
            s = s * __expf(m - M) + s2 * __expf(m2 - M);
            m = M;
        }
        if (tx == 0) { g_rm[blockIdx.x] = m; g_rs[blockIdx.x] = s; }
    }
    __syncthreads();
    if (wid == 0) T_DEALLOC(tmem, 512);
#else
    // ---------- generic scalar fallback: maha' = x . (B~ x~) ----------
    extern __shared__ char msm[];
    float* sW = (float*)msm;                  // [64*68] fp32 B~ for current k
    __shared__ float s_ck[KK];
    __shared__ float s_wm[9], s_ws[9];
    int tx = threadIdx.x, wid = tx >> 5, lane = tx & 31;
    if (tx < KK) s_ck[tx] = g_ck[tx];

    float xt[65];
    if (tx < 256) {
        const float4* xs = (const float4*)(X + ((size_t)blockIdx.x * 256 + tx) * DD);
#pragma unroll
        for (int i = 0; i < 16; i++) {
            float4 v = xs[i];
            xt[4 * i] = v.x; xt[4 * i + 1] = v.y; xt[4 * i + 2] = v.z; xt[4 * i + 3] = v.w;
        }
        xt[64] = 1.0f;
    }

    float mx = -INFINITY, sm = 0.f;
#pragma unroll 1
    for (int k = 0; k < KK; k++) {
        __syncthreads();
        const float4* src = (const float4*)g_Wf[k];
        for (int i = tx; i < 64 * 68 / 4; i += 288) ((float4*)sW)[i] = src[i];
        __syncthreads();
        if (tx < 256) {
            float maha = 0.f;
            for (int j = 0; j < 64; j++) {
                const float* row = sW + j * 68;
                float z = 0.f;
#pragma unroll
                for (int c = 0; c < 65; c++) z = fmaf(row[c], xt[c], z);
                maha = fmaf(xt[j], z, maha);
            }
            float logp = s_ck[k] - 0.5f * maha;
            if (logp > mx) { sm = fmaf(sm, __expf(mx - logp), 1.0f); mx = logp; }
            else           { sm += __expf(logp - mx); }
        }
    }
    if (tx < 256) {
#pragma unroll
        for (int o = 16; o; o >>= 1) {
            float m2 = __shfl_xor_sync(0xffffffffu, mx, o);
            float s2 = __shfl_xor_sync(0xffffffffu, sm, o);
            float M = fmaxf(mx, m2);
            sm = sm * __expf(mx - M) + s2 * __expf(m2 - M);
            mx = M;
        }
        if (lane == 0) { s_wm[wid] = mx; s_ws[wid] = sm; }
    }
    __syncthreads();
    if (tx < 8) {
        float m = s_wm[tx], s = s_ws[tx];
#pragma unroll
        for (int o = 4; o; o >>= 1) {
            float m2 = __shfl_xor_sync(0xffu, m, o);
            float s2 = __shfl_xor_sync(0xffu, s, o);
            float M = fmaxf(m, m2);
            s = s * __expf(m - M) + s2 * __expf(m2 - M);
            m = M;
        }
        if (tx == 0) { g_rm[blockIdx.x] = m; g_rs[blockIdx.x] = s; }
    }
#endif
}

// ============= final reduce: -logsumexp over 128 CTA partials =============
__global__ void reduce_kernel(float* __restrict__ out) {
    __shared__ float rm[4], rs[4];
    int tx = threadIdx.x, lane = tx & 31, wid = tx >> 5;
    float m = g_rm[tx], s = g_rs[tx];
#pragma unroll
    for (int o = 16; o; o >>= 1) {
        float m2 = __shfl_xor_sync(0xffffffffu, m, o);
        float s2 = __shfl_xor_sync(0xffffffffu, s, o);
        float M = fmaxf(m, m2);
        s = s * __expf(m - M) + s2 * __expf(m2 - M);
        m = M;
    }
    if (lane == 0) { rm[wid] = m; rs[wid] = s; }
    __syncthreads();
    if (tx < 4) {
        float mm = rm[tx], ss = rs[tx];
#pragma unroll
        for (int o = 2; o; o >>= 1) {
            float m2 = __shfl_xor_sync(0xfu, mm, o);
            float s2 = __shfl_xor_sync(0xfu, ss, o);
            float M = fmaxf(mm, m2);
            ss = ss * __expf(mm - M) + s2 * __expf(m2 - M);
            mm = M;
        }
        if (tx == 0) out[0] = -(mm + logf(ss));
    }
}

// ---------------- launch ----------------
extern "C" void kernel_launch(void* const* d_in, const int* in_sizes, int n_in,
                              void* d_out, int out_size) {
    const float* X  = (const float*)d_in[0];
    const float* mu = (const float*)d_in[1];
    const float* L  = (const float*)d_in[2];
    const float* w  = (const float*)d_in[3];
    float* out = (float*)d_out;

    static int attr_done = 0;
    if (!attr_done) {
        cudaFuncSetAttribute(setup_kernel, cudaFuncAttributeMaxDynamicSharedMemorySize, 34048);
        cudaFuncSetAttribute(main_kernel, cudaFuncAttributeMaxDynamicSharedMemorySize, 99328);
        attr_done = 1;
    }

    setup_kernel<<<KK, 1024, 34048>>>(L, mu, w);
    main_kernel<<<NPTS / 256, 288, 99328>>>(X);
    reduce_kernel<<<1, 128>>>(out);
}